// round 2
// baseline (speedup 1.0000x reference)
#include <cuda_runtime.h>
#include <math.h>

// Problem dims (fixed by the dataset)
#define NX   4096
#define NY   4096
#define DIN  1024
#define HID  1024
#define DOUT 1024

// Scratch: __device__ globals (allocation-free, zero-init -> .bss)
__device__ float g_Q[(size_t)NX * HID];
__device__ float g_K[(size_t)NY * HID];
__device__ float g_V[(size_t)NY * DOUT];
__device__ float g_S[(size_t)NX * NY];

// ---------------------------------------------------------------------------
// Tiled SGEMM: C[M,N] = scale * (A[M,K] @ op(B)) + bias[N]
//   BT = true : B is [N,K] row-major  (C = A @ B^T)   -- projections, scores
//   BT = false: B is [K,N] row-major  (C = A @ B)     -- attn @ V
// BM=BN=128, BK=8, 256 threads, 8x8 register tile per thread.
// All dims must be multiples of the tile sizes (true here).
// ---------------------------------------------------------------------------
template <bool BT>
__global__ __launch_bounds__(256)
void sgemm_kernel(const float* __restrict__ A,
                  const float* __restrict__ B,
                  const float* __restrict__ bias,
                  float* __restrict__ C,
                  int M, int N, int K, float scale)
{
    constexpr int BM = 128, BN = 128, BK = 8, TM = 8, TN = 8;

    __shared__ float As[BK][BM];
    __shared__ float Bs[BK][BN];

    const int tid  = threadIdx.x;
    const int rm   = tid >> 4;          // 0..15
    const int rn   = tid & 15;          // 0..15
    const int row0 = blockIdx.y * BM;
    const int col0 = blockIdx.x * BN;

    // A-tile (and BT B-tile) loader: 128 rows x 8 cols, one float4 per thread
    const int la_row = tid >> 1;        // 0..127
    const int la_col = (tid & 1) * 4;   // 0 or 4
    // NN B-tile loader: 8 rows x 128 cols, one float4 per thread
    const int lb_row = tid >> 5;        // 0..7
    const int lb_col = (tid & 31) * 4;  // 0..124

    float acc[TM][TN];
#pragma unroll
    for (int i = 0; i < TM; i++)
#pragma unroll
        for (int j = 0; j < TN; j++) acc[i][j] = 0.0f;

    for (int k0 = 0; k0 < K; k0 += BK) {
        // Load A tile (transposed into smem)
        float4 av = *reinterpret_cast<const float4*>(
            A + (size_t)(row0 + la_row) * K + k0 + la_col);
        As[la_col + 0][la_row] = av.x;
        As[la_col + 1][la_row] = av.y;
        As[la_col + 2][la_row] = av.z;
        As[la_col + 3][la_row] = av.w;

        if (BT) {
            // B is [N,K]: same access pattern as A
            float4 bv = *reinterpret_cast<const float4*>(
                B + (size_t)(col0 + la_row) * K + k0 + la_col);
            Bs[la_col + 0][la_row] = bv.x;
            Bs[la_col + 1][la_row] = bv.y;
            Bs[la_col + 2][la_row] = bv.z;
            Bs[la_col + 3][la_row] = bv.w;
        } else {
            // B is [K,N]: rows are contiguous in N
            float4 bv = *reinterpret_cast<const float4*>(
                B + (size_t)(k0 + lb_row) * N + col0 + lb_col);
            *reinterpret_cast<float4*>(&Bs[lb_row][lb_col]) = bv;
        }
        __syncthreads();

#pragma unroll
        for (int k = 0; k < BK; k++) {
            float ra[TM], rb[TN];
#pragma unroll
            for (int i = 0; i < TM; i++) ra[i] = As[k][rm * TM + i];
#pragma unroll
            for (int j = 0; j < TN; j++) rb[j] = Bs[k][rn * TN + j];
#pragma unroll
            for (int i = 0; i < TM; i++)
#pragma unroll
                for (int j = 0; j < TN; j++)
                    acc[i][j] = fmaf(ra[i], rb[j], acc[i][j]);
        }
        __syncthreads();
    }

    // Epilogue: scale, +bias, store (float4)
#pragma unroll
    for (int i = 0; i < TM; i++) {
        const int r = row0 + rm * TM + i;
#pragma unroll
        for (int j = 0; j < TN; j += 4) {
            const int c = col0 + rn * TN + j;
            float4 o;
            float b0 = bias ? bias[c + 0] : 0.0f;
            float b1 = bias ? bias[c + 1] : 0.0f;
            float b2 = bias ? bias[c + 2] : 0.0f;
            float b3 = bias ? bias[c + 3] : 0.0f;
            o.x = acc[i][j + 0] * scale + b0;
            o.y = acc[i][j + 1] * scale + b1;
            o.z = acc[i][j + 2] * scale + b2;
            o.w = acc[i][j + 3] * scale + b3;
            *reinterpret_cast<float4*>(C + (size_t)r * N + c) = o;
        }
    }
}

// ---------------------------------------------------------------------------
// Row softmax over N=4096 columns. One block (256 threads) per row,
// 16 elements per thread held in registers.
// ---------------------------------------------------------------------------
__device__ __forceinline__ float warp_max(float v) {
#pragma unroll
    for (int o = 16; o > 0; o >>= 1) v = fmaxf(v, __shfl_xor_sync(0xffffffffu, v, o));
    return v;
}
__device__ __forceinline__ float warp_sum(float v) {
#pragma unroll
    for (int o = 16; o > 0; o >>= 1) v += __shfl_xor_sync(0xffffffffu, v, o);
    return v;
}

__global__ __launch_bounds__(256)
void softmax_rows_kernel(float* __restrict__ S, int N)
{
    constexpr int T = 256;
    constexpr int PER = 4096 / T;  // 16
    const int row = blockIdx.x;
    float* p = S + (size_t)row * N;
    const int tid = threadIdx.x;
    const int wid = tid >> 5, lid = tid & 31;

    __shared__ float red[8];

    float v[PER];
    float mx = -INFINITY;
#pragma unroll
    for (int i = 0; i < PER; i++) {
        v[i] = p[tid + i * T];
        mx = fmaxf(mx, v[i]);
    }
    mx = warp_max(mx);
    if (lid == 0) red[wid] = mx;
    __syncthreads();
    {
        float m = (lid < 8) ? red[lid] : -INFINITY;
        m = warp_max(m);
        mx = __shfl_sync(0xffffffffu, m, 0);
    }

    float sum = 0.0f;
#pragma unroll
    for (int i = 0; i < PER; i++) {
        v[i] = __expf(v[i] - mx);
        sum += v[i];
    }
    sum = warp_sum(sum);
    __syncthreads();
    if (lid == 0) red[wid] = sum;
    __syncthreads();
    {
        float s = (lid < 8) ? red[lid] : 0.0f;
        s = warp_sum(s);
        sum = __shfl_sync(0xffffffffu, s, 0);
    }

    const float inv = 1.0f / sum;
#pragma unroll
    for (int i = 0; i < PER; i++) p[tid + i * T] = v[i] * inv;
}

// ---------------------------------------------------------------------------
// kernel_launch: x, y, Wq, bq, Wk, bk, Wv, bv  ->  out [NX, DOUT] fp32
// ---------------------------------------------------------------------------
extern "C" void kernel_launch(void* const* d_in, const int* in_sizes, int n_in,
                              void* d_out, int out_size)
{
    (void)in_sizes; (void)n_in; (void)out_size;
    const float* x  = (const float*)d_in[0];
    const float* y  = (const float*)d_in[1];
    const float* Wq = (const float*)d_in[2];
    const float* bq = (const float*)d_in[3];
    const float* Wk = (const float*)d_in[4];
    const float* bk = (const float*)d_in[5];
    const float* Wv = (const float*)d_in[6];
    const float* bv = (const float*)d_in[7];
    float* out = (float*)d_out;

    float *Q, *K, *V, *S;
    cudaGetSymbolAddress((void**)&Q, g_Q);
    cudaGetSymbolAddress((void**)&K, g_K);
    cudaGetSymbolAddress((void**)&V, g_V);
    cudaGetSymbolAddress((void**)&S, g_S);

    const float inv_sqrt_h = 1.0f / 32.0f;  // 1/sqrt(1024)

    // Projections: C = A @ W^T + b   (NT)
    {
        dim3 grid(HID / 128, NX / 128);
        sgemm_kernel<true><<<grid, 256>>>(x, Wq, bq, Q, NX, HID, DIN, 1.0f);
    }
    {
        dim3 grid(HID / 128, NY / 128);
        sgemm_kernel<true><<<grid, 256>>>(y, Wk, bk, K, NY, HID, DIN, 1.0f);
    }
    {
        dim3 grid(DOUT / 128, NY / 128);
        sgemm_kernel<true><<<grid, 256>>>(y, Wv, bv, V, NY, DOUT, DIN, 1.0f);
    }

    // Scores: S = (Q @ K^T) / 32    (NT)
    {
        dim3 grid(NY / 128, NX / 128);
        sgemm_kernel<true><<<grid, 256>>>(Q, K, nullptr, S, NX, NY, HID, inv_sqrt_h);
    }

    // Row softmax
    softmax_rows_kernel<<<NX, 256>>>(S, NY);

    // Output: out = S @ V           (NN)
    {
        dim3 grid(DOUT / 128, NX / 128);
        sgemm_kernel<false><<<grid, 256>>>(S, V, nullptr, out, NX, DOUT, NY, 1.0f);
    }
}

// round 5
// speedup vs baseline: 2.7065x; 2.7065x over previous
#include <cuda_runtime.h>
#include <cuda_bf16.h>
#include <math.h>
#include <stdint.h>

// Problem dims (fixed by the dataset)
#define NX   4096
#define NY   4096
#define DIN  1024
#define HID  1024
#define DOUT 1024

// Scratch: __device__ globals (allocation-free)
__device__ float g_Q [(size_t)NX * HID];
__device__ float g_K [(size_t)NY * HID];
__device__ float g_VT[(size_t)DOUT * NY];   // V^T = Wv @ y^T  [1024 x 4096]
__device__ float g_S [(size_t)NX * NY];

// ---------------------------------------------------------------------------
// Helpers
// ---------------------------------------------------------------------------
__device__ __forceinline__ uint32_t smem_u32(const void* p) {
    uint32_t a;
    asm("{ .reg .u64 t; cvta.to.shared.u64 t, %1; cvt.u32.u64 %0, t; }" : "=r"(a) : "l"(p));
    return a;
}

__device__ __forceinline__ void ldm_x4(uint32_t* r, uint32_t addr) {
    asm volatile("ldmatrix.sync.aligned.m8n8.x4.shared.b16 {%0,%1,%2,%3}, [%4];"
                 : "=r"(r[0]), "=r"(r[1]), "=r"(r[2]), "=r"(r[3]) : "r"(addr));
}

__device__ __forceinline__ void mma_bf16(float* c, const uint32_t* a,
                                         uint32_t b0, uint32_t b1) {
    asm volatile(
        "mma.sync.aligned.m16n8k16.row.col.f32.bf16.bf16.f32 "
        "{%0,%1,%2,%3}, {%4,%5,%6,%7}, {%8,%9}, {%0,%1,%2,%3};"
        : "+f"(c[0]), "+f"(c[1]), "+f"(c[2]), "+f"(c[3])
        : "r"(a[0]), "r"(a[1]), "r"(a[2]), "r"(a[3]), "r"(b0), "r"(b1));
}

// fp32 pair -> (hi bf16x2, lo bf16x2); x lands in the low 16 bits
__device__ __forceinline__ void cvt_split(float x, float y, uint32_t& h, uint32_t& l) {
    asm("cvt.rn.bf16x2.f32 %0, %1, %2;" : "=r"(h) : "f"(y), "f"(x));
    float hx = __uint_as_float(h << 16);
    float hy = __uint_as_float(h & 0xffff0000u);
    asm("cvt.rn.bf16x2.f32 %0, %1, %2;" : "=r"(l) : "f"(y - hy), "f"(x - hx));
}

// ---------------------------------------------------------------------------
// bf16-split tensor-core GEMM (mma.sync):
//   C[M,N] = scale*(A[M,K] @ B[N,K]^T) + bias_col[N] + bias_row[M]
// BM=BN=128, BK=32, 256 threads (8 warps, 4x2), warp tile 32x64.
// ---------------------------------------------------------------------------
#define PITCH 40                     // bf16 elems per smem row (80 B, conflict-free)
#define T_AHI 0
#define T_ALO (128 * PITCH * 2)      // 10240
#define T_BHI (2 * 128 * PITCH * 2)  // 20480
#define T_BLO (3 * 128 * PITCH * 2)  // 30720
#define STAGE_BYTES (4 * 128 * PITCH * 2)   // 40960
#define SM_TOTAL (2 * STAGE_BYTES)          // 81920

__global__ __launch_bounds__(256, 1)
void gemm_mma(const float* __restrict__ A, const float* __restrict__ B,
              const float* __restrict__ bias_col, const float* __restrict__ bias_row,
              float* __restrict__ C, int M, int N, int K, float scale)
{
    extern __shared__ __align__(16) char smem[];
    const uint32_t sbase = smem_u32(smem);

    const int tid    = threadIdx.x;
    const int lane   = tid & 31;
    const int wid    = tid >> 5;
    const int warp_m = wid & 3;          // 0..3  (M slabs of 32)
    const int warp_n = wid >> 2;         // 0..1  (N slabs of 64)
    const int row0   = blockIdx.y * 128;
    const int col0   = blockIdx.x * 128;

    const float* Ab = A + (size_t)row0 * K;
    const float* Bb = B + (size_t)col0 * K;

    // Loader geometry: 1024 float4 per 128x32 tile -> 4 per thread
    const int l_row = tid >> 3;          // wrong granularity fixed below per-iter
    (void)l_row;

    float acc[2][8][4];
#pragma unroll
    for (int mf = 0; mf < 2; mf++)
#pragma unroll
        for (int nf = 0; nf < 8; nf++)
#pragma unroll
            for (int e = 0; e < 4; e++) acc[mf][nf][e] = 0.0f;

    // ldmatrix source addresses (fixed per thread, vary by stage/kk/frag)
    const int a_row = lane & 15;
    const int a_kh  = (lane >> 4) << 3;          // 0 or 8
    const int bg    = lane >> 3;                 // 0..3
    const int b_nrow = ((bg >> 1) << 3) + (lane & 7);
    const int b_kh   = (bg & 1) << 3;

    const int nch = K >> 5;
    float4 pa[4], pb[4];

    // ---- prefetch + store chunk 0 ----
#pragma unroll
    for (int it = 0; it < 4; it++) {
        int idx = tid + it * 256;                // 0..1023
        int r = idx >> 3, c4 = idx & 7;
        pa[it] = *reinterpret_cast<const float4*>(Ab + (size_t)r * K + c4 * 4);
        pb[it] = *reinterpret_cast<const float4*>(Bb + (size_t)r * K + c4 * 4);
    }
    {
        char* st = smem;                          // stage 0
#pragma unroll
        for (int it = 0; it < 4; it++) {
            int idx = tid + it * 256;
            int r = idx >> 3, c4 = idx & 7;
            uint32_t off = (r * PITCH + c4 * 4) * 2;
            uint32_t h0, l0, h1, l1;
            cvt_split(pa[it].x, pa[it].y, h0, l0);
            cvt_split(pa[it].z, pa[it].w, h1, l1);
            *reinterpret_cast<uint2*>(st + T_AHI + off) = make_uint2(h0, h1);
            *reinterpret_cast<uint2*>(st + T_ALO + off) = make_uint2(l0, l1);
            cvt_split(pb[it].x, pb[it].y, h0, l0);
            cvt_split(pb[it].z, pb[it].w, h1, l1);
            *reinterpret_cast<uint2*>(st + T_BHI + off) = make_uint2(h0, h1);
            *reinterpret_cast<uint2*>(st + T_BLO + off) = make_uint2(l0, l1);
        }
    }
    __syncthreads();

    for (int c = 0; c < nch; c++) {
        // prefetch chunk c+1 into regs (LDGs overlap the MMAs below)
        if (c + 1 < nch) {
            const float* Ac = Ab + (c + 1) * 32;
            const float* Bc = Bb + (c + 1) * 32;
#pragma unroll
            for (int it = 0; it < 4; it++) {
                int idx = tid + it * 256;
                int r = idx >> 3, c4 = idx & 7;
                pa[it] = *reinterpret_cast<const float4*>(Ac + (size_t)r * K + c4 * 4);
                pb[it] = *reinterpret_cast<const float4*>(Bc + (size_t)r * K + c4 * 4);
            }
        }

        // ---- compute chunk c from stage c&1 ----
        const uint32_t st = sbase + (c & 1) * STAGE_BYTES;
#pragma unroll
        for (int kk = 0; kk < 32; kk += 16) {
            uint32_t ah[2][4], al[2][4];
#pragma unroll
            for (int mf = 0; mf < 2; mf++) {
                uint32_t ra = st + ((warp_m * 32 + mf * 16 + a_row) * PITCH + kk + a_kh) * 2;
                ldm_x4(ah[mf], ra + T_AHI);
                ldm_x4(al[mf], ra + T_ALO);
            }
#pragma unroll
            for (int ng = 0; ng < 4; ng++) {     // n-frags 2ng, 2ng+1
                uint32_t bh[4], bl[4];
                uint32_t rb = st + ((warp_n * 64 + ng * 16 + b_nrow) * PITCH + kk + b_kh) * 2;
                ldm_x4(bh, rb + T_BHI);
                ldm_x4(bl, rb + T_BLO);
#pragma unroll
                for (int mf = 0; mf < 2; mf++) {
#pragma unroll
                    for (int s = 0; s < 2; s++) {
                        float* cc = acc[mf][2 * ng + s];
                        mma_bf16(cc, ah[mf], bh[2 * s], bh[2 * s + 1]);
                        mma_bf16(cc, ah[mf], bl[2 * s], bl[2 * s + 1]);
                        mma_bf16(cc, al[mf], bh[2 * s], bh[2 * s + 1]);
                    }
                }
            }
        }

        // ---- store prefetched chunk into the other stage ----
        if (c + 1 < nch) {
            char* so = smem + ((c + 1) & 1) * STAGE_BYTES;
#pragma unroll
            for (int it = 0; it < 4; it++) {
                int idx = tid + it * 256;
                int r = idx >> 3, c4 = idx & 7;
                uint32_t off = (r * PITCH + c4 * 4) * 2;
                uint32_t h0, l0, h1, l1;
                cvt_split(pa[it].x, pa[it].y, h0, l0);
                cvt_split(pa[it].z, pa[it].w, h1, l1);
                *reinterpret_cast<uint2*>(so + T_AHI + off) = make_uint2(h0, h1);
                *reinterpret_cast<uint2*>(so + T_ALO + off) = make_uint2(l0, l1);
                cvt_split(pb[it].x, pb[it].y, h0, l0);
                cvt_split(pb[it].z, pb[it].w, h1, l1);
                *reinterpret_cast<uint2*>(so + T_BHI + off) = make_uint2(h0, h1);
                *reinterpret_cast<uint2*>(so + T_BLO + off) = make_uint2(l0, l1);
            }
            __syncthreads();
        }
    }

    // ---- epilogue: C frags -> gmem ----
    const int mrow = lane >> 2;          // 0..7
    const int ncol = (lane & 3) * 2;
#pragma unroll
    for (int mf = 0; mf < 2; mf++) {
        const int m0 = row0 + warp_m * 32 + mf * 16 + mrow;
        const float br0 = bias_row ? bias_row[m0]     : 0.0f;
        const float br8 = bias_row ? bias_row[m0 + 8] : 0.0f;
#pragma unroll
        for (int nf = 0; nf < 8; nf++) {
            const int n = col0 + warp_n * 64 + nf * 8 + ncol;
            float bc0 = 0.0f, bc1 = 0.0f;
            if (bias_col) { bc0 = bias_col[n]; bc1 = bias_col[n + 1]; }
            float* cc = acc[mf][nf];
            float2 v0 = make_float2(cc[0] * scale + bc0 + br0, cc[1] * scale + bc1 + br0);
            float2 v1 = make_float2(cc[2] * scale + bc0 + br8, cc[3] * scale + bc1 + br8);
            *reinterpret_cast<float2*>(C + (size_t)m0 * N + n)       = v0;
            *reinterpret_cast<float2*>(C + (size_t)(m0 + 8) * N + n) = v1;
        }
    }
}

// ---------------------------------------------------------------------------
// Row softmax over N=4096 columns
// ---------------------------------------------------------------------------
__device__ __forceinline__ float warp_max(float v) {
#pragma unroll
    for (int o = 16; o > 0; o >>= 1) v = fmaxf(v, __shfl_xor_sync(0xffffffffu, v, o));
    return v;
}
__device__ __forceinline__ float warp_sum(float v) {
#pragma unroll
    for (int o = 16; o > 0; o >>= 1) v += __shfl_xor_sync(0xffffffffu, v, o);
    return v;
}

__global__ __launch_bounds__(256)
void softmax_rows_kernel(float* __restrict__ S, int N)
{
    constexpr int T = 256;
    constexpr int PER = 4096 / T;
    const int row = blockIdx.x;
    float* p = S + (size_t)row * N;
    const int tid = threadIdx.x;
    const int wid = tid >> 5, lid = tid & 31;
    __shared__ float red[8];

    float v[PER];
    float mx = -INFINITY;
#pragma unroll
    for (int i = 0; i < PER; i++) { v[i] = p[tid + i * T]; mx = fmaxf(mx, v[i]); }
    mx = warp_max(mx);
    if (lid == 0) red[wid] = mx;
    __syncthreads();
    { float m = (lid < 8) ? red[lid] : -INFINITY; m = warp_max(m); mx = __shfl_sync(0xffffffffu, m, 0); }

    float sum = 0.0f;
#pragma unroll
    for (int i = 0; i < PER; i++) { v[i] = __expf(v[i] - mx); sum += v[i]; }
    sum = warp_sum(sum);
    __syncthreads();
    if (lid == 0) red[wid] = sum;
    __syncthreads();
    { float s = (lid < 8) ? red[lid] : 0.0f; s = warp_sum(s); sum = __shfl_sync(0xffffffffu, s, 0); }

    const float inv = 1.0f / sum;
#pragma unroll
    for (int i = 0; i < PER; i++) p[tid + i * T] = v[i] * inv;
}

// ---------------------------------------------------------------------------
// kernel_launch
// ---------------------------------------------------------------------------
extern "C" void kernel_launch(void* const* d_in, const int* in_sizes, int n_in,
                              void* d_out, int out_size)
{
    (void)in_sizes; (void)n_in; (void)out_size;
    const float* x  = (const float*)d_in[0];
    const float* y  = (const float*)d_in[1];
    const float* Wq = (const float*)d_in[2];
    const float* bq = (const float*)d_in[3];
    const float* Wk = (const float*)d_in[4];
    const float* bk = (const float*)d_in[5];
    const float* Wv = (const float*)d_in[6];
    const float* bv = (const float*)d_in[7];
    float* out = (float*)d_out;

    float *Q, *Kp, *VT, *S;
    cudaGetSymbolAddress((void**)&Q,  g_Q);
    cudaGetSymbolAddress((void**)&Kp, g_K);
    cudaGetSymbolAddress((void**)&VT, g_VT);
    cudaGetSymbolAddress((void**)&S,  g_S);

    cudaFuncSetAttribute(gemm_mma, cudaFuncAttributeMaxDynamicSharedMemorySize, SM_TOTAL);

    const float inv_sqrt_h = 1.0f / 32.0f;

    // Q = x @ Wq^T + bq          [4096,1024]
    gemm_mma<<<dim3(HID/128, NX/128), 256, SM_TOTAL>>>(x, Wq, bq, nullptr, Q, NX, HID, DIN, 1.0f);
    // K = y @ Wk^T + bk          [4096,1024]
    gemm_mma<<<dim3(HID/128, NY/128), 256, SM_TOTAL>>>(y, Wk, bk, nullptr, Kp, NY, HID, DIN, 1.0f);
    // V^T = Wv @ y^T + bv(row)   [1024,4096]
    gemm_mma<<<dim3(NY/128, DOUT/128), 256, SM_TOTAL>>>(Wv, y, nullptr, bv, VT, DOUT, NY, DIN, 1.0f);
    // S = (Q @ K^T)/32           [4096,4096]
    gemm_mma<<<dim3(NY/128, NX/128), 256, SM_TOTAL>>>(Q, Kp, nullptr, nullptr, S, NX, NY, HID, inv_sqrt_h);
    // softmax rows
    softmax_rows_kernel<<<NX, 256>>>(S, NY);
    // out = attn @ V = S @ VT^T  [4096,1024]
    gemm_mma<<<dim3(DOUT/128, NX/128), 256, SM_TOTAL>>>(S, VT, nullptr, nullptr, out, NX, DOUT, NY, 1.0f);
}

// round 6
// speedup vs baseline: 2.7189x; 1.0046x over previous
#include <cuda_runtime.h>
#include <cuda_bf16.h>
#include <math.h>
#include <stdint.h>

// Problem dims (fixed by the dataset)
#define NX   4096
#define NY   4096
#define DIN  1024
#define HID  1024
#define DOUT 1024

typedef __nv_bfloat16 bf16;

// ---------------------------------------------------------------------------
// Scratch: __device__ globals (allocation-free)
// ---------------------------------------------------------------------------
// pre-split inputs
__device__ bf16 g_xh[(size_t)NX * DIN],  g_xl[(size_t)NX * DIN];
__device__ bf16 g_yh[(size_t)NY * DIN],  g_yl[(size_t)NY * DIN];
__device__ bf16 g_Wqh[(size_t)HID * DIN], g_Wql[(size_t)HID * DIN];
__device__ bf16 g_Wkh[(size_t)HID * DIN], g_Wkl[(size_t)HID * DIN];
__device__ bf16 g_Wvh[(size_t)DOUT * DIN], g_Wvl[(size_t)DOUT * DIN];
// intermediates (bf16 hi/lo)
__device__ bf16 g_Qh[(size_t)NX * HID],  g_Ql[(size_t)NX * HID];
__device__ bf16 g_Kh[(size_t)NY * HID],  g_Kl[(size_t)NY * HID];
__device__ bf16 g_VTh[(size_t)DOUT * NY], g_VTl[(size_t)DOUT * NY];
__device__ bf16 g_Ph[(size_t)NX * NY],   g_Pl[(size_t)NX * NY];
// scores (fp32, softmax needs full precision)
__device__ float g_S[(size_t)NX * NY];

// ---------------------------------------------------------------------------
// Helpers
// ---------------------------------------------------------------------------
__device__ __forceinline__ uint32_t smem_u32(const void* p) {
    uint32_t a;
    asm("{ .reg .u64 t; cvta.to.shared.u64 t, %1; cvt.u32.u64 %0, t; }" : "=r"(a) : "l"(p));
    return a;
}
__device__ __forceinline__ void ldm_x4(uint32_t* r, uint32_t addr) {
    asm volatile("ldmatrix.sync.aligned.m8n8.x4.shared.b16 {%0,%1,%2,%3}, [%4];"
                 : "=r"(r[0]), "=r"(r[1]), "=r"(r[2]), "=r"(r[3]) : "r"(addr));
}
__device__ __forceinline__ void mma_bf16(float* c, const uint32_t* a,
                                         uint32_t b0, uint32_t b1) {
    asm volatile(
        "mma.sync.aligned.m16n8k16.row.col.f32.bf16.bf16.f32 "
        "{%0,%1,%2,%3}, {%4,%5,%6,%7}, {%8,%9}, {%0,%1,%2,%3};"
        : "+f"(c[0]), "+f"(c[1]), "+f"(c[2]), "+f"(c[3])
        : "r"(a[0]), "r"(a[1]), "r"(a[2]), "r"(a[3]), "r"(b0), "r"(b1));
}
// fp32 pair -> (hi bf16x2, lo bf16x2); x lands in the low 16 bits
__device__ __forceinline__ void cvt_split(float x, float y, uint32_t& h, uint32_t& l) {
    asm("cvt.rn.bf16x2.f32 %0, %1, %2;" : "=r"(h) : "f"(y), "f"(x));
    float hx = __uint_as_float(h << 16);
    float hy = __uint_as_float(h & 0xffff0000u);
    asm("cvt.rn.bf16x2.f32 %0, %1, %2;" : "=r"(l) : "f"(y - hy), "f"(x - hx));
}
__device__ __forceinline__ void cpa16(uint32_t d, const void* s) {
    asm volatile("cp.async.cg.shared.global [%0], [%1], 16;" :: "r"(d), "l"(s) : "memory");
}
#define CP_COMMIT() asm volatile("cp.async.commit_group;" ::: "memory")
#define CP_WAIT1()  asm volatile("cp.async.wait_group 1;" ::: "memory")

// ---------------------------------------------------------------------------
// Elementwise fp32 -> (hi, lo) bf16 split.  n must be a multiple of 4.
// ---------------------------------------------------------------------------
__global__ __launch_bounds__(256)
void split_kernel(const float* __restrict__ in, bf16* __restrict__ hi,
                  bf16* __restrict__ lo, int n4)
{
    int i = blockIdx.x * 256 + threadIdx.x;
    if (i >= n4) return;
    float4 v = reinterpret_cast<const float4*>(in)[i];
    uint32_t h0, l0, h1, l1;
    cvt_split(v.x, v.y, h0, l0);
    cvt_split(v.z, v.w, h1, l1);
    reinterpret_cast<uint2*>(hi)[i] = make_uint2(h0, h1);
    reinterpret_cast<uint2*>(lo)[i] = make_uint2(l0, l1);
}

// ---------------------------------------------------------------------------
// bf16-split tensor-core GEMM (pre-split operands, cp.async pipeline):
//   acc = A @ B^T  (A = Ahi+Alo [M,K], B = Bhi+Blo [N,K], both K-major bf16)
//   v   = scale*acc + bias_col[N] + bias_row[M]
//   if Cf:  Cf = v (fp32);  if Chi: (Chi, Clo) = bf16 split of v
// BM=BN=128, BK=32, 256 threads (8 warps, 4x2), warp tile 32x64, 2 CTAs/SM.
// ---------------------------------------------------------------------------
#define PITCH 40                      // bf16 elems per smem row (80 B)
#define T_AHI 0
#define T_ALO (128 * PITCH * 2)       // 10240
#define T_BHI (2 * 128 * PITCH * 2)
#define T_BLO (3 * 128 * PITCH * 2)
#define STAGE_BYTES (4 * 128 * PITCH * 2)   // 40960
#define SM_TOTAL (2 * STAGE_BYTES)          // 81920

__global__ __launch_bounds__(256, 2)
void gemm_bf16(const bf16* __restrict__ Ahi, const bf16* __restrict__ Alo,
               const bf16* __restrict__ Bhi, const bf16* __restrict__ Blo,
               const float* __restrict__ bias_col, const float* __restrict__ bias_row,
               float* __restrict__ Cf, bf16* __restrict__ Chi, bf16* __restrict__ Clo,
               int M, int N, int K, float scale)
{
    extern __shared__ __align__(128) char smem[];
    const uint32_t sbase = smem_u32(smem);

    const int tid    = threadIdx.x;
    const int lane   = tid & 31;
    const int wid    = tid >> 5;
    const int warp_m = wid & 3;
    const int warp_n = wid >> 2;
    const int row0   = blockIdx.y * 128;
    const int col0   = blockIdx.x * 128;

    const bf16* pAh = Ahi + (size_t)row0 * K;
    const bf16* pAl = Alo + (size_t)row0 * K;
    const bf16* pBh = Bhi + (size_t)col0 * K;
    const bf16* pBl = Blo + (size_t)col0 * K;

    // loader geometry: 2 iters x (row = idx>>2, seg = idx&3), 16B per cp.async
    const int l_r0 = tid >> 2;          // rows for it=0: 0..63
    const int l_sg = (tid & 3) * 8;     // bf16 offset within row (8 elems = 16B)

    float acc[2][8][4];
#pragma unroll
    for (int mf = 0; mf < 2; mf++)
#pragma unroll
        for (int nf = 0; nf < 8; nf++)
#pragma unroll
            for (int e = 0; e < 4; e++) acc[mf][nf][e] = 0.0f;

    // ldmatrix addressing (identical geometry to the validated R5 kernel)
    const int a_row  = lane & 15;
    const int a_kh   = (lane >> 4) << 3;
    const int bg     = lane >> 3;
    const int b_nrow = ((bg >> 1) << 3) + (lane & 7);
    const int b_kh   = (bg & 1) << 3;

    const int nch = K >> 5;

    // ---- issue chunk 0 into stage 0 ----
    {
        const uint32_t st = sbase;
#pragma unroll
        for (int it = 0; it < 2; it++) {
            const int r = l_r0 + it * 64;
            const size_t go = (size_t)r * K + l_sg;
            const uint32_t so = (uint32_t)(r * PITCH + l_sg) * 2;
            cpa16(st + T_AHI + so, pAh + go);
            cpa16(st + T_ALO + so, pAl + go);
            cpa16(st + T_BHI + so, pBh + go);
            cpa16(st + T_BLO + so, pBl + go);
        }
        CP_COMMIT();
    }

    for (int c = 0; c < nch; c++) {
        // issue chunk c+1 into the other stage (its previous readers finished
        // before the trailing __syncthreads of iteration c-1)
        if (c + 1 < nch) {
            const uint32_t st = sbase + ((c + 1) & 1) * STAGE_BYTES;
            const int kofs = (c + 1) * 32;
#pragma unroll
            for (int it = 0; it < 2; it++) {
                const int r = l_r0 + it * 64;
                const size_t go = (size_t)r * K + kofs + l_sg;
                const uint32_t so = (uint32_t)(r * PITCH + l_sg) * 2;
                cpa16(st + T_AHI + so, pAh + go);
                cpa16(st + T_ALO + so, pAl + go);
                cpa16(st + T_BHI + so, pBh + go);
                cpa16(st + T_BLO + so, pBl + go);
            }
        }
        CP_COMMIT();          // one group per iteration (possibly empty)
        CP_WAIT1();           // chunk c's group is complete
        __syncthreads();

        // ---- compute chunk c from stage c&1 ----
        const uint32_t st = sbase + (c & 1) * STAGE_BYTES;
#pragma unroll
        for (int kk = 0; kk < 32; kk += 16) {
            uint32_t ah[2][4], al[2][4];
#pragma unroll
            for (int mf = 0; mf < 2; mf++) {
                uint32_t ra = st + ((warp_m * 32 + mf * 16 + a_row) * PITCH + kk + a_kh) * 2;
                ldm_x4(ah[mf], ra + T_AHI);
                ldm_x4(al[mf], ra + T_ALO);
            }
#pragma unroll
            for (int ng = 0; ng < 4; ng++) {
                uint32_t bh[4], bl[4];
                uint32_t rb = st + ((warp_n * 64 + ng * 16 + b_nrow) * PITCH + kk + b_kh) * 2;
                ldm_x4(bh, rb + T_BHI);
                ldm_x4(bl, rb + T_BLO);
#pragma unroll
                for (int mf = 0; mf < 2; mf++) {
#pragma unroll
                    for (int s = 0; s < 2; s++) {
                        float* cc = acc[mf][2 * ng + s];
                        mma_bf16(cc, ah[mf], bh[2 * s], bh[2 * s + 1]);
                        mma_bf16(cc, ah[mf], bl[2 * s], bl[2 * s + 1]);
                        mma_bf16(cc, al[mf], bh[2 * s], bh[2 * s + 1]);
                    }
                }
            }
        }
        __syncthreads();      // readers done before next iter overwrites this stage
    }

    // ---- epilogue ----
    const int mrow = lane >> 2;
    const int ncol = (lane & 3) * 2;
#pragma unroll
    for (int mf = 0; mf < 2; mf++) {
        const int m0 = row0 + warp_m * 32 + mf * 16 + mrow;
        const float br0 = bias_row ? bias_row[m0]     : 0.0f;
        const float br8 = bias_row ? bias_row[m0 + 8] : 0.0f;
#pragma unroll
        for (int nf = 0; nf < 8; nf++) {
            const int n = col0 + warp_n * 64 + nf * 8 + ncol;
            float bc0 = 0.0f, bc1 = 0.0f;
            if (bias_col) { bc0 = bias_col[n]; bc1 = bias_col[n + 1]; }
            float* cc = acc[mf][nf];
            float v00 = cc[0] * scale + bc0 + br0;
            float v01 = cc[1] * scale + bc1 + br0;
            float v10 = cc[2] * scale + bc0 + br8;
            float v11 = cc[3] * scale + bc1 + br8;
            if (Cf) {
                *reinterpret_cast<float2*>(Cf + (size_t)m0 * N + n)       = make_float2(v00, v01);
                *reinterpret_cast<float2*>(Cf + (size_t)(m0 + 8) * N + n) = make_float2(v10, v11);
            }
            if (Chi) {
                uint32_t h, l;
                cvt_split(v00, v01, h, l);
                *reinterpret_cast<uint32_t*>(Chi + (size_t)m0 * N + n) = h;
                *reinterpret_cast<uint32_t*>(Clo + (size_t)m0 * N + n) = l;
                cvt_split(v10, v11, h, l);
                *reinterpret_cast<uint32_t*>(Chi + (size_t)(m0 + 8) * N + n) = h;
                *reinterpret_cast<uint32_t*>(Clo + (size_t)(m0 + 8) * N + n) = l;
            }
        }
    }
}

// ---------------------------------------------------------------------------
// Row softmax over N=4096 fp32 scores -> hi/lo bf16 probabilities
// ---------------------------------------------------------------------------
__device__ __forceinline__ float warp_max(float v) {
#pragma unroll
    for (int o = 16; o > 0; o >>= 1) v = fmaxf(v, __shfl_xor_sync(0xffffffffu, v, o));
    return v;
}
__device__ __forceinline__ float warp_sum(float v) {
#pragma unroll
    for (int o = 16; o > 0; o >>= 1) v += __shfl_xor_sync(0xffffffffu, v, o);
    return v;
}

__global__ __launch_bounds__(256)
void softmax_rows_kernel(const float* __restrict__ S, bf16* __restrict__ Ph,
                         bf16* __restrict__ Pl, int N)
{
    constexpr int T = 256;
    constexpr int PER = 4096 / T;
    const int row = blockIdx.x;
    const float* p = S + (size_t)row * N;
    bf16* ph = Ph + (size_t)row * N;
    bf16* pl = Pl + (size_t)row * N;
    const int tid = threadIdx.x;
    const int wid = tid >> 5, lid = tid & 31;
    __shared__ float red[8];

    float v[PER];
    float mx = -INFINITY;
#pragma unroll
    for (int i = 0; i < PER; i++) { v[i] = p[tid + i * T]; mx = fmaxf(mx, v[i]); }
    mx = warp_max(mx);
    if (lid == 0) red[wid] = mx;
    __syncthreads();
    { float m = (lid < 8) ? red[lid] : -INFINITY; m = warp_max(m); mx = __shfl_sync(0xffffffffu, m, 0); }

    float sum = 0.0f;
#pragma unroll
    for (int i = 0; i < PER; i++) { v[i] = __expf(v[i] - mx); sum += v[i]; }
    sum = warp_sum(sum);
    __syncthreads();
    if (lid == 0) red[wid] = sum;
    __syncthreads();
    { float s = (lid < 8) ? red[lid] : 0.0f; s = warp_sum(s); sum = __shfl_sync(0xffffffffu, s, 0); }

    const float inv = 1.0f / sum;
#pragma unroll
    for (int i = 0; i < PER; i++) {
        float pv = v[i] * inv;
        bf16 h = __float2bfloat16_rn(pv);
        bf16 l = __float2bfloat16_rn(pv - __bfloat162float(h));
        ph[tid + i * T] = h;
        pl[tid + i * T] = l;
    }
}

// ---------------------------------------------------------------------------
// kernel_launch
// ---------------------------------------------------------------------------
extern "C" void kernel_launch(void* const* d_in, const int* in_sizes, int n_in,
                              void* d_out, int out_size)
{
    (void)in_sizes; (void)n_in; (void)out_size;
    const float* x  = (const float*)d_in[0];
    const float* y  = (const float*)d_in[1];
    const float* Wq = (const float*)d_in[2];
    const float* bq = (const float*)d_in[3];
    const float* Wk = (const float*)d_in[4];
    const float* bk = (const float*)d_in[5];
    const float* Wv = (const float*)d_in[6];
    const float* bv = (const float*)d_in[7];
    float* out = (float*)d_out;

    bf16 *xh, *xl, *yh, *yl, *Wqh, *Wql, *Wkh, *Wkl, *Wvh, *Wvl;
    bf16 *Qh, *Ql, *Kh, *Kl, *VTh, *VTl, *Ph, *Pl;
    float* S;
    cudaGetSymbolAddress((void**)&xh,  g_xh);  cudaGetSymbolAddress((void**)&xl,  g_xl);
    cudaGetSymbolAddress((void**)&yh,  g_yh);  cudaGetSymbolAddress((void**)&yl,  g_yl);
    cudaGetSymbolAddress((void**)&Wqh, g_Wqh); cudaGetSymbolAddress((void**)&Wql, g_Wql);
    cudaGetSymbolAddress((void**)&Wkh, g_Wkh); cudaGetSymbolAddress((void**)&Wkl, g_Wkl);
    cudaGetSymbolAddress((void**)&Wvh, g_Wvh); cudaGetSymbolAddress((void**)&Wvl, g_Wvl);
    cudaGetSymbolAddress((void**)&Qh,  g_Qh);  cudaGetSymbolAddress((void**)&Ql,  g_Ql);
    cudaGetSymbolAddress((void**)&Kh,  g_Kh);  cudaGetSymbolAddress((void**)&Kl,  g_Kl);
    cudaGetSymbolAddress((void**)&VTh, g_VTh); cudaGetSymbolAddress((void**)&VTl, g_VTl);
    cudaGetSymbolAddress((void**)&Ph,  g_Ph);  cudaGetSymbolAddress((void**)&Pl,  g_Pl);
    cudaGetSymbolAddress((void**)&S,   g_S);

    cudaFuncSetAttribute(gemm_bf16, cudaFuncAttributeMaxDynamicSharedMemorySize, SM_TOTAL);

    const float inv_sqrt_h = 1.0f / 32.0f;

    // Pre-split inputs to hi/lo bf16
    {
        int n4;
        n4 = NX * DIN / 4;  split_kernel<<<(n4 + 255) / 256, 256>>>(x,  xh,  xl,  n4);
        n4 = NY * DIN / 4;  split_kernel<<<(n4 + 255) / 256, 256>>>(y,  yh,  yl,  n4);
        n4 = HID * DIN / 4; split_kernel<<<(n4 + 255) / 256, 256>>>(Wq, Wqh, Wql, n4);
        n4 = HID * DIN / 4; split_kernel<<<(n4 + 255) / 256, 256>>>(Wk, Wkh, Wkl, n4);
        n4 = DOUT * DIN / 4; split_kernel<<<(n4 + 255) / 256, 256>>>(Wv, Wvh, Wvl, n4);
    }

    // Q = x @ Wq^T + bq     -> bf16 hi/lo   [4096,1024]
    gemm_bf16<<<dim3(HID/128, NX/128), 256, SM_TOTAL>>>(
        xh, xl, Wqh, Wql, bq, nullptr, nullptr, Qh, Ql, NX, HID, DIN, 1.0f);
    // K = y @ Wk^T + bk     -> bf16 hi/lo   [4096,1024]
    gemm_bf16<<<dim3(HID/128, NY/128), 256, SM_TOTAL>>>(
        yh, yl, Wkh, Wkl, bk, nullptr, nullptr, Kh, Kl, NY, HID, DIN, 1.0f);
    // V^T = Wv @ y^T + bv(row) -> bf16 hi/lo [1024,4096]
    gemm_bf16<<<dim3(NY/128, DOUT/128), 256, SM_TOTAL>>>(
        Wvh, Wvl, yh, yl, nullptr, bv, nullptr, VTh, VTl, DOUT, NY, DIN, 1.0f);
    // S = (Q @ K^T)/32      -> fp32         [4096,4096]
    gemm_bf16<<<dim3(NY/128, NX/128), 256, SM_TOTAL>>>(
        Qh, Ql, Kh, Kl, nullptr, nullptr, S, nullptr, nullptr, NX, NY, HID, inv_sqrt_h);
    // softmax rows -> attn hi/lo bf16
    softmax_rows_kernel<<<NX, 256>>>(S, Ph, Pl, NY);
    // out = attn @ V = P @ VT^T -> fp32     [4096,1024]
    gemm_bf16<<<dim3(DOUT/128, NX/128), 256, SM_TOTAL>>>(
        Ph, Pl, VTh, VTl, nullptr, nullptr, out, nullptr, nullptr, NX, DOUT, NY, 1.0f);
}